// round 5
// baseline (speedup 1.0000x reference)
#include <cuda_runtime.h>

typedef unsigned long long u64;

#define BLK   128
#define XSTR  129   // padded SMEM stride for the transposed x tile

#define OFF_S0 0        // 136*16 symmetric w0  (scaled a2)
#define OFF_S2 2176     // 136*16 symmetric w2  (scaled a2/sqrt3)
#define OFF_S4 4352     // 136*16 symmetric w4  (scaled a1)
#define OFF_A3 6528     // 120*16 antisym  w3   (scaled a1/sqrt2)
#define OFF_W1 8448     // 256*16 w1            (scaled a1)
#define W_TOTAL 12544
#define SMEM_FLOATS (W_TOTAL + 64 * XSTR)
#define SMEM_BYTES  (SMEM_FLOATS * 4)

#define A1F    0.0625f                  // 1/sqrt(16*16)
#define A2F    0.04419417382415922f     // 1/sqrt(16*16*2)
#define A2_3F  0.02551551815399144f     // A2/sqrt(3)
#define A1S2F  0.04419417382415922f     // A1/sqrt(2)
#define S2F    0.7071067811865476f
#define R2F    1.4142135623730951f
#define IS6F   0.4082482904638630f      // 1/sqrt(6)

__device__ float g_ws[W_TOTAL];

// ---------------------------------------------------------------------------
// Weight preprocessing: fold symmetrization + all alpha / CG norm constants.
// ---------------------------------------------------------------------------
__global__ void prep_kernel(const float* __restrict__ w0, const float* __restrict__ w1,
                            const float* __restrict__ w2, const float* __restrict__ w3,
                            const float* __restrict__ w4)
{
    int idx = blockIdx.x * blockDim.x + threadIdx.x;   // (u,v,w) flattened, 4096
    if (idx >= 4096) return;
    int w = idx & 15;
    int v = (idx >> 4) & 15;
    int u = idx >> 8;
    int sidx = ((v * 16 + u) << 4) + w;                // (v,u,w)

    g_ws[OFF_W1 + idx] = A1F * w1[idx];

    if (u <= v) {
        int p = u * 16 - (u * (u - 1)) / 2 + (v - u);  // sym pair index (u-major, v>=u)
        float f0 = (u == v) ? w0[idx] : (w0[idx] + w0[sidx]);
        float f2 = (u == v) ? w2[idx] : (w2[idx] + w2[sidx]);
        float f4 = (u == v) ? w4[idx] : (w4[idx] + w4[sidx]);
        g_ws[OFF_S0 + p * 16 + w] = A2F   * f0;
        g_ws[OFF_S2 + p * 16 + w] = A2_3F * f2;
        g_ws[OFF_S4 + p * 16 + w] = A1F   * f4;
    }
    if (u < v) {
        int pa = 15 * u - (u * (u - 1)) / 2 + (v - u - 1);  // antisym pair index
        g_ws[OFF_A3 + pa * 16 + w] = A1S2F * (w3[idx] - w3[sidx]);
    }
}

// ---------------------------------------------------------------------------
// Packed-fp32 helpers (fma.rn.f32x2 is PTX-only on sm_103a; ptxas won't fuse)
// ---------------------------------------------------------------------------
__device__ __forceinline__ u64 dup2(float s)
{
    unsigned int b = __float_as_uint(s);
    u64 r;
    asm("mov.b64 %0, {%1, %1};" : "=l"(r) : "r"(b));
    return r;
}
__device__ __forceinline__ void fma2(u64& d, u64 a, u64 b)
{
    asm("fma.rn.f32x2 %0, %1, %2, %0;" : "+l"(d) : "l"(a), "l"(b));
}
__device__ __forceinline__ void unpk(u64 v, float& lo, float& hi)
{
    unsigned int l, h;
    asm("mov.b64 {%0, %1}, %2;" : "=r"(l), "=r"(h) : "l"(v));
    lo = __uint_as_float(l);
    hi = __uint_as_float(h);
}

// acc[0..7] += f * w[0..15]   (w read as 4x LDS.128, broadcast across warp)
__device__ __forceinline__ void axpy16(u64* acc, const float* wb, u64 f)
{
    const ulonglong2* wr = reinterpret_cast<const ulonglong2*>(wb);
#pragma unroll
    for (int q = 0; q < 4; q++) {
        ulonglong2 wv = wr[q];
        fma2(acc[2 * q + 0], f, wv.x);
        fma2(acc[2 * q + 1], f, wv.y);
    }
}
// 3 features sharing one weight row (o_1o / o_1e)
__device__ __forceinline__ void axpy16x3(u64* acc, const float* wb, u64 f0, u64 f1, u64 f2)
{
    const ulonglong2* wr = reinterpret_cast<const ulonglong2*>(wb);
#pragma unroll
    for (int q = 0; q < 4; q++) {
        ulonglong2 wv = wr[q];
        fma2(acc[0 + 2 * q], f0, wv.x);  fma2(acc[0 + 2 * q + 1], f0, wv.y);
        fma2(acc[8 + 2 * q], f1, wv.x);  fma2(acc[8 + 2 * q + 1], f1, wv.y);
        fma2(acc[16 + 2 * q], f2, wv.x); fma2(acc[16 + 2 * q + 1], f2, wv.y);
    }
}
// 5 features sharing one weight row (o_2e)
__device__ __forceinline__ void axpy16x5(u64* acc, const float* wb,
                                         u64 f0, u64 f1, u64 f2, u64 f3, u64 f4)
{
    const ulonglong2* wr = reinterpret_cast<const ulonglong2*>(wb);
#pragma unroll
    for (int q = 0; q < 4; q++) {
        ulonglong2 wv = wr[q];
        fma2(acc[0 + 2 * q], f0, wv.x);  fma2(acc[0 + 2 * q + 1], f0, wv.y);
        fma2(acc[8 + 2 * q], f1, wv.x);  fma2(acc[8 + 2 * q + 1], f1, wv.y);
        fma2(acc[16 + 2 * q], f2, wv.x); fma2(acc[16 + 2 * q + 1], f2, wv.y);
        fma2(acc[24 + 2 * q], f3, wv.x); fma2(acc[24 + 2 * q + 1], f3, wv.y);
        fma2(acc[32 + 2 * q], f4, wv.x); fma2(acc[32 + 2 * q + 1], f4, wv.y);
    }
}

// ---------------------------------------------------------------------------
// Main kernel: one thread per row, w-channels packed pairwise in f32x2.
// ---------------------------------------------------------------------------
__global__ __launch_bounds__(BLK, 2)
void tsq_kernel(const float* __restrict__ x, float* __restrict__ out, int n)
{
    extern __shared__ float smem[];
    float* ws = smem;               // 12544 floats of preprocessed weights
    float* xs = smem + W_TOTAL;     // 64 x 128 transposed x tile (stride 129)
    int tid = threadIdx.x;

    // stage weights (broadcast-read later, so SMEM copy amortizes fully)
    {
        const float4* gw = reinterpret_cast<const float4*>(g_ws);
        float4* sw = reinterpret_cast<float4*>(ws);
        for (int i = tid; i < W_TOTAL / 4; i += BLK) sw[i] = gw[i];
    }
    // stage x tile, transposed to [feature][row] so pair loops are conflict-free
    int row0 = blockIdx.x * BLK;
    {
        const float4* x4 = reinterpret_cast<const float4*>(x);
#pragma unroll
        for (int i = 0; i < 16; i++) {
            int lin = i * BLK + tid;
            int r = lin >> 4, c = lin & 15;
            float4 val = make_float4(0.f, 0.f, 0.f, 0.f);
            if (row0 + r < n) val = x4[(size_t)(row0 + r) * 16 + c];
            xs[(4 * c + 0) * XSTR + r] = val.x;
            xs[(4 * c + 1) * XSTR + r] = val.y;
            xs[(4 * c + 2) * XSTR + r] = val.z;
            xs[(4 * c + 3) * XSTR + r] = val.w;
        }
    }
    __syncthreads();

    int z = row0 + tid;
    if (z >= n) return;
    float* o = out + (size_t)z * 192;

    // ===== fused symmetric pass: o_0e (paths 0+2), o_1e (path 3), o_2e (path 4)
    u64 acc0[8], acc1e[24], acc2e[40];
#pragma unroll
    for (int k = 0; k < 8; k++)  acc0[k] = 0ULL;
#pragma unroll
    for (int k = 0; k < 24; k++) acc1e[k] = 0ULL;
#pragma unroll
    for (int k = 0; k < 40; k++) acc2e[k] = 0ULL;

    const float* s0r = ws + OFF_S0;
    const float* s2r = ws + OFF_S2;
    const float* s4r = ws + OFF_S4;
    const float* a3r = ws + OFF_A3;

    for (int u = 0; u < 16; u++) {
        float a0 = xs[u * XSTR + tid];
        float ax = xs[(16 + 3 * u + 0) * XSTR + tid];
        float ay = xs[(16 + 3 * u + 1) * XSTR + tid];
        float az = xs[(16 + 3 * u + 2) * XSTR + tid];

        {   // diagonal pair (v == u): cross vanishes
            float pxx = ax * ax, pyy = ay * ay, pzz = az * az;
            float s0 = a0 * a0;
            float d  = pxx + pyy + pzz;
            float q0 = R2F * (ax * ay);
            float q1 = R2F * (ay * az);
            float q3 = R2F * (ax * az);
            float q2 = IS6F * (2.f * pzz - pxx - pyy);
            float q4 = S2F  * (pxx - pyy);
            axpy16(acc0, s0r, dup2(s0));
            axpy16(acc0, s2r, dup2(d));
            axpy16x5(acc2e, s4r, dup2(q0), dup2(q1), dup2(q2), dup2(q3), dup2(q4));
            s0r += 16; s2r += 16; s4r += 16;
        }
        for (int v = u + 1; v < 16; v++) {
            float b0 = xs[v * XSTR + tid];
            float bx = xs[(16 + 3 * v + 0) * XSTR + tid];
            float by = xs[(16 + 3 * v + 1) * XSTR + tid];
            float bz = xs[(16 + 3 * v + 2) * XSTR + tid];
            float pxx = ax * bx, pyy = ay * by, pzz = az * bz;
            float pxy = ax * by, pyx = ay * bx;
            float pyz = ay * bz, pzy = az * by;
            float pxz = ax * bz, pzx = az * bx;
            float s0 = a0 * b0;
            float d  = pxx + pyy + pzz;
            float cx = pyz - pzy, cy = pzx - pxz, cz = pxy - pyx;
            float q0 = S2F * (pxy + pyx);
            float q1 = S2F * (pyz + pzy);
            float q3 = S2F * (pxz + pzx);
            float q2 = IS6F * (2.f * pzz - pxx - pyy);
            float q4 = S2F  * (pxx - pyy);
            axpy16(acc0, s0r, dup2(s0));
            axpy16(acc0, s2r, dup2(d));
            axpy16x3(acc1e, a3r, dup2(cx), dup2(cy), dup2(cz));
            axpy16x5(acc2e, s4r, dup2(q0), dup2(q1), dup2(q2), dup2(q3), dup2(q4));
            s0r += 16; s2r += 16; s4r += 16; a3r += 16;
        }
    }

    // o_0e: out[0..15], layout [w]
    {
        float ob[16];
#pragma unroll
        for (int j = 0; j < 8; j++) unpk(acc0[j], ob[2 * j], ob[2 * j + 1]);
        float4* o4 = reinterpret_cast<float4*>(o);
#pragma unroll
        for (int j = 0; j < 4; j++)
            o4[j] = make_float4(ob[4 * j], ob[4 * j + 1], ob[4 * j + 2], ob[4 * j + 3]);
    }
    // o_1e: out[64..111], layout [w*3 + m]
    {
        float ob[48];
#pragma unroll
        for (int m = 0; m < 3; m++)
#pragma unroll
            for (int j = 0; j < 8; j++) {
                float lo, hi;
                unpk(acc1e[m * 8 + j], lo, hi);
                ob[(2 * j) * 3 + m] = lo;
                ob[(2 * j + 1) * 3 + m] = hi;
            }
        float4* o4 = reinterpret_cast<float4*>(o + 64);
#pragma unroll
        for (int j = 0; j < 12; j++)
            o4[j] = make_float4(ob[4 * j], ob[4 * j + 1], ob[4 * j + 2], ob[4 * j + 3]);
    }
    // o_2e: out[112..191], layout [w*5 + m]
    {
        float ob[80];
#pragma unroll
        for (int m = 0; m < 5; m++)
#pragma unroll
            for (int j = 0; j < 8; j++) {
                float lo, hi;
                unpk(acc2e[m * 8 + j], lo, hi);
                ob[(2 * j) * 5 + m] = lo;
                ob[(2 * j + 1) * 5 + m] = hi;
            }
        float4* o4 = reinterpret_cast<float4*>(o + 112);
#pragma unroll
        for (int j = 0; j < 20; j++)
            o4[j] = make_float4(ob[4 * j], ob[4 * j + 1], ob[4 * j + 2], ob[4 * j + 3]);
    }

    // ===== path 1 (0e x 1o -> 1o): full 256-pair rectangle
    {
        u64 acc1[24];
#pragma unroll
        for (int k = 0; k < 24; k++) acc1[k] = 0ULL;

        float a0r[16];
#pragma unroll
        for (int u = 0; u < 16; u++) a0r[u] = xs[u * XSTR + tid];

        for (int v = 0; v < 16; v++) {
            float bx = xs[(16 + 3 * v + 0) * XSTR + tid];
            float by = xs[(16 + 3 * v + 1) * XSTR + tid];
            float bz = xs[(16 + 3 * v + 2) * XSTR + tid];
            const float* wr = ws + OFF_W1 + v * 16;
#pragma unroll
            for (int u = 0; u < 16; u++) {
                float a0 = a0r[u];
                axpy16x3(acc1, wr + u * 256, dup2(a0 * bx), dup2(a0 * by), dup2(a0 * bz));
            }
        }
        // o_1o: out[16..63], layout [w*3 + m]
        float ob[48];
#pragma unroll
        for (int m = 0; m < 3; m++)
#pragma unroll
            for (int j = 0; j < 8; j++) {
                float lo, hi;
                unpk(acc1[m * 8 + j], lo, hi);
                ob[(2 * j) * 3 + m] = lo;
                ob[(2 * j + 1) * 3 + m] = hi;
            }
        float4* o4 = reinterpret_cast<float4*>(o + 16);
#pragma unroll
        for (int j = 0; j < 12; j++)
            o4[j] = make_float4(ob[4 * j], ob[4 * j + 1], ob[4 * j + 2], ob[4 * j + 3]);
    }
}

// ---------------------------------------------------------------------------
extern "C" void kernel_launch(void* const* d_in, const int* in_sizes, int n_in,
                              void* d_out, int out_size)
{
    const float* x  = (const float*)d_in[0];
    const float* w0 = (const float*)d_in[1];
    const float* w1 = (const float*)d_in[2];
    const float* w2 = (const float*)d_in[3];
    const float* w3 = (const float*)d_in[4];
    const float* w4 = (const float*)d_in[5];
    float* out = (float*)d_out;
    int n = in_sizes[0] / 64;

    cudaFuncSetAttribute(tsq_kernel, cudaFuncAttributeMaxDynamicSharedMemorySize, SMEM_BYTES);

    prep_kernel<<<16, 256>>>(w0, w1, w2, w3, w4);
    tsq_kernel<<<(n + BLK - 1) / BLK, BLK, SMEM_BYTES>>>(x, out, n);
}

// round 8
// speedup vs baseline: 1.0342x; 1.0342x over previous
#include <cuda_runtime.h>

typedef unsigned long long u64;

#define BLK   256
#define ROWS  128
#define XSTR  129   // padded SMEM stride for the transposed x tile

#define OFF_S0 0        // 136*16 symmetric w0  (scaled a2)
#define OFF_S2 2176     // 136*16 symmetric w2  (scaled a2/sqrt3)
#define OFF_S4 4352     // 136*16 symmetric w4  (scaled a1)
#define OFF_A3 6528     // 120*16 antisym  w3   (scaled a1/sqrt2)
#define OFF_W1 8448     // 256*16 w1            (scaled a1)
#define W_TOTAL 12544
#define SMEM_FLOATS (W_TOTAL + 64 * XSTR)
#define SMEM_BYTES  (SMEM_FLOATS * 4)

#define A1F    0.0625f                  // 1/sqrt(16*16)
#define A2F    0.04419417382415922f     // 1/sqrt(16*16*2)
#define A2_3F  0.02551551815399144f     // A2/sqrt(3)
#define A1S2F  0.04419417382415922f     // A1/sqrt(2)
#define S2F    0.7071067811865476f
#define R2F    1.4142135623730951f
#define IS6F   0.4082482904638630f      // 1/sqrt(6)

__device__ float g_ws[W_TOTAL];

// ---------------------------------------------------------------------------
// Weight preprocessing: fold symmetrization + all alpha / CG norm constants.
// ---------------------------------------------------------------------------
__global__ void prep_kernel(const float* __restrict__ w0, const float* __restrict__ w1,
                            const float* __restrict__ w2, const float* __restrict__ w3,
                            const float* __restrict__ w4)
{
    int idx = blockIdx.x * blockDim.x + threadIdx.x;   // (u,v,w) flattened, 4096
    if (idx >= 4096) return;
    int w = idx & 15;
    int v = (idx >> 4) & 15;
    int u = idx >> 8;
    int sidx = ((v * 16 + u) << 4) + w;                // (v,u,w)

    g_ws[OFF_W1 + idx] = A1F * w1[idx];

    if (u <= v) {
        int p = u * 16 - (u * (u - 1)) / 2 + (v - u);  // sym pair index (u-major, v>=u)
        float f0 = (u == v) ? w0[idx] : (w0[idx] + w0[sidx]);
        float f2 = (u == v) ? w2[idx] : (w2[idx] + w2[sidx]);
        float f4 = (u == v) ? w4[idx] : (w4[idx] + w4[sidx]);
        g_ws[OFF_S0 + p * 16 + w] = A2F   * f0;
        g_ws[OFF_S2 + p * 16 + w] = A2_3F * f2;
        g_ws[OFF_S4 + p * 16 + w] = A1F   * f4;
    }
    if (u < v) {
        int pa = 15 * u - (u * (u - 1)) / 2 + (v - u - 1);  // antisym pair index
        g_ws[OFF_A3 + pa * 16 + w] = A1S2F * (w3[idx] - w3[sidx]);
    }
}

// ---------------------------------------------------------------------------
// Packed-fp32 helpers (fma.rn.f32x2 is PTX-only on sm_103a; ptxas won't fuse)
// ---------------------------------------------------------------------------
__device__ __forceinline__ u64 dup2(float s)
{
    unsigned int b = __float_as_uint(s);
    u64 r;
    asm("mov.b64 %0, {%1, %1};" : "=l"(r) : "r"(b));
    return r;
}
__device__ __forceinline__ void fma2(u64& d, u64 a, u64 b)
{
    asm("fma.rn.f32x2 %0, %1, %2, %0;" : "+l"(d) : "l"(a), "l"(b));
}
__device__ __forceinline__ u64 mul2(u64 a, u64 b)
{
    u64 d;
    asm("mul.rn.f32x2 %0, %1, %2;" : "=l"(d) : "l"(a), "l"(b));
    return d;
}
__device__ __forceinline__ void unpk(u64 v, float& lo, float& hi)
{
    unsigned int l, h;
    asm("mov.b64 {%0, %1}, %2;" : "=r"(l), "=r"(h) : "l"(v));
    lo = __uint_as_float(l);
    hi = __uint_as_float(h);
}

// acc[0..7] += f * w[0..15]   (w read as 4x LDS.128, broadcast across warp)
__device__ __forceinline__ void axpy16(u64* acc, const float* wb, u64 f)
{
    const ulonglong2* wr = reinterpret_cast<const ulonglong2*>(wb);
#pragma unroll
    for (int q = 0; q < 4; q++) {
        ulonglong2 wv = wr[q];
        fma2(acc[2 * q + 0], f, wv.x);
        fma2(acc[2 * q + 1], f, wv.y);
    }
}
// 3 features sharing one weight row (o_1e)
__device__ __forceinline__ void axpy16x3(u64* acc, const float* wb, u64 f0, u64 f1, u64 f2)
{
    const ulonglong2* wr = reinterpret_cast<const ulonglong2*>(wb);
#pragma unroll
    for (int q = 0; q < 4; q++) {
        ulonglong2 wv = wr[q];
        fma2(acc[0 + 2 * q], f0, wv.x);  fma2(acc[0 + 2 * q + 1], f0, wv.y);
        fma2(acc[8 + 2 * q], f1, wv.x);  fma2(acc[8 + 2 * q + 1], f1, wv.y);
        fma2(acc[16 + 2 * q], f2, wv.x); fma2(acc[16 + 2 * q + 1], f2, wv.y);
    }
}
// 5 features sharing one weight row (o_2e)
__device__ __forceinline__ void axpy16x5(u64* acc, const float* wb,
                                         u64 f0, u64 f1, u64 f2, u64 f3, u64 f4)
{
    const ulonglong2* wr = reinterpret_cast<const ulonglong2*>(wb);
#pragma unroll
    for (int q = 0; q < 4; q++) {
        ulonglong2 wv = wr[q];
        fma2(acc[0 + 2 * q], f0, wv.x);  fma2(acc[0 + 2 * q + 1], f0, wv.y);
        fma2(acc[8 + 2 * q], f1, wv.x);  fma2(acc[8 + 2 * q + 1], f1, wv.y);
        fma2(acc[16 + 2 * q], f2, wv.x); fma2(acc[16 + 2 * q + 1], f2, wv.y);
        fma2(acc[24 + 2 * q], f3, wv.x); fma2(acc[24 + 2 * q + 1], f3, wv.y);
        fma2(acc[32 + 2 * q], f4, wv.x); fma2(acc[32 + 2 * q + 1], f4, wv.y);
    }
}

// ---------------------------------------------------------------------------
// Main kernel: 2 threads per row (role = path split), w packed pairwise f32x2.
//   role 0 (warps 0-3): o_2e sym pass + o_1o[w 0..7]
//   role 1 (warps 4-7): o_0e + o_1e sym pass + o_1o[w 8..15]
// ---------------------------------------------------------------------------
__global__ __launch_bounds__(BLK, 2)
void tsq_kernel(const float* __restrict__ x, float* __restrict__ out, int n)
{
    extern __shared__ float smem[];
    float* ws = smem;               // 12544 floats of preprocessed weights
    float* xs = smem + W_TOTAL;     // 64 x 128 transposed x tile (stride 129)
    int tid = threadIdx.x;

    // stage weights (broadcast-read later)
    {
        const float4* gw = reinterpret_cast<const float4*>(g_ws);
        float4* sw = reinterpret_cast<float4*>(ws);
        for (int i = tid; i < W_TOTAL / 4; i += BLK) sw[i] = gw[i];
    }
    // stage x tile, transposed to [feature][row]
    int row0 = blockIdx.x * ROWS;
    {
        const float4* x4 = reinterpret_cast<const float4*>(x);
#pragma unroll
        for (int i = 0; i < 8; i++) {
            int lin = i * BLK + tid;         // 2048 = 128 rows * 16 float4
            int r = lin >> 4, c = lin & 15;
            float4 val = make_float4(0.f, 0.f, 0.f, 0.f);
            if (row0 + r < n) val = x4[(size_t)(row0 + r) * 16 + c];
            xs[(4 * c + 0) * XSTR + r] = val.x;
            xs[(4 * c + 1) * XSTR + r] = val.y;
            xs[(4 * c + 2) * XSTR + r] = val.z;
            xs[(4 * c + 3) * XSTR + r] = val.w;
        }
    }
    __syncthreads();

    int role = tid >> 7;        // uniform per warp
    int r    = tid & 127;
    int z = row0 + r;
    if (z >= n) return;
    float* o = out + (size_t)z * 192;

    if (role == 0) {
        // ===== o_2e (path 4), symmetric pairs
        u64 acc2e[40];
#pragma unroll
        for (int k = 0; k < 40; k++) acc2e[k] = 0ULL;
        const float* s4r = ws + OFF_S4;

        for (int u = 0; u < 16; u++) {
            float ax = xs[(16 + 3 * u + 0) * XSTR + r];
            float ay = xs[(16 + 3 * u + 1) * XSTR + r];
            float az = xs[(16 + 3 * u + 2) * XSTR + r];
            {   // diagonal pair
                float pxx = ax * ax, pyy = ay * ay, pzz = az * az;
                float q0 = R2F * (ax * ay);
                float q1 = R2F * (ay * az);
                float q3 = R2F * (ax * az);
                float q2 = IS6F * (2.f * pzz - pxx - pyy);
                float q4 = S2F  * (pxx - pyy);
                axpy16x5(acc2e, s4r, dup2(q0), dup2(q1), dup2(q2), dup2(q3), dup2(q4));
                s4r += 16;
            }
            for (int v = u + 1; v < 16; v++) {
                float bx = xs[(16 + 3 * v + 0) * XSTR + r];
                float by = xs[(16 + 3 * v + 1) * XSTR + r];
                float bz = xs[(16 + 3 * v + 2) * XSTR + r];
                float pxx = ax * bx, pyy = ay * by, pzz = az * bz;
                float q0 = S2F * (ax * by + ay * bx);
                float q1 = S2F * (ay * bz + az * by);
                float q3 = S2F * (ax * bz + az * bx);
                float q2 = IS6F * (2.f * pzz - pxx - pyy);
                float q4 = S2F  * (pxx - pyy);
                axpy16x5(acc2e, s4r, dup2(q0), dup2(q1), dup2(q2), dup2(q3), dup2(q4));
                s4r += 16;
            }
        }
        // o_2e: out[112..191], layout [w*5 + m]
        float ob[80];
#pragma unroll
        for (int m = 0; m < 5; m++)
#pragma unroll
            for (int j = 0; j < 8; j++) {
                float lo, hi;
                unpk(acc2e[m * 8 + j], lo, hi);
                ob[(2 * j) * 5 + m] = lo;
                ob[(2 * j + 1) * 5 + m] = hi;
            }
        float4* o4 = reinterpret_cast<float4*>(o + 112);
#pragma unroll
        for (int j = 0; j < 20; j++)
            o4[j] = make_float4(ob[4 * j], ob[4 * j + 1], ob[4 * j + 2], ob[4 * j + 3]);
    } else {
        // ===== o_0e (paths 0+2) and o_1e (path 3), symmetric pairs
        u64 acc0[8], acc1e[24];
#pragma unroll
        for (int k = 0; k < 8; k++)  acc0[k] = 0ULL;
#pragma unroll
        for (int k = 0; k < 24; k++) acc1e[k] = 0ULL;
        const float* s0r = ws + OFF_S0;
        const float* s2r = ws + OFF_S2;
        const float* a3r = ws + OFF_A3;

        for (int u = 0; u < 16; u++) {
            float a0 = xs[u * XSTR + r];
            float ax = xs[(16 + 3 * u + 0) * XSTR + r];
            float ay = xs[(16 + 3 * u + 1) * XSTR + r];
            float az = xs[(16 + 3 * u + 2) * XSTR + r];
            {   // diagonal pair: cross vanishes
                float s0 = a0 * a0;
                float d  = ax * ax + ay * ay + az * az;
                axpy16(acc0, s0r, dup2(s0));
                axpy16(acc0, s2r, dup2(d));
                s0r += 16; s2r += 16;
            }
            for (int v = u + 1; v < 16; v++) {
                float b0 = xs[v * XSTR + r];
                float bx = xs[(16 + 3 * v + 0) * XSTR + r];
                float by = xs[(16 + 3 * v + 1) * XSTR + r];
                float bz = xs[(16 + 3 * v + 2) * XSTR + r];
                float s0 = a0 * b0;
                float d  = ax * bx + ay * by + az * bz;
                float cx = ay * bz - az * by;
                float cy = az * bx - ax * bz;
                float cz = ax * by - ay * bx;
                axpy16(acc0, s0r, dup2(s0));
                axpy16(acc0, s2r, dup2(d));
                axpy16x3(acc1e, a3r, dup2(cx), dup2(cy), dup2(cz));
                s0r += 16; s2r += 16; a3r += 16;
            }
        }
        // o_0e: out[0..15]
        {
            float ob[16];
#pragma unroll
            for (int j = 0; j < 8; j++) unpk(acc0[j], ob[2 * j], ob[2 * j + 1]);
            float4* o4 = reinterpret_cast<float4*>(o);
#pragma unroll
            for (int j = 0; j < 4; j++)
                o4[j] = make_float4(ob[4 * j], ob[4 * j + 1], ob[4 * j + 2], ob[4 * j + 3]);
        }
        // o_1e: out[64..111], layout [w*3 + m]
        {
            float ob[48];
#pragma unroll
            for (int m = 0; m < 3; m++)
#pragma unroll
                for (int j = 0; j < 8; j++) {
                    float lo, hi;
                    unpk(acc1e[m * 8 + j], lo, hi);
                    ob[(2 * j) * 3 + m] = lo;
                    ob[(2 * j + 1) * 3 + m] = hi;
                }
            float4* o4 = reinterpret_cast<float4*>(o + 64);
#pragma unroll
            for (int j = 0; j < 12; j++)
                o4[j] = make_float4(ob[4 * j], ob[4 * j + 1], ob[4 * j + 2], ob[4 * j + 3]);
        }
    }

    // ===== path 1 (0e x 1o -> 1o), FACTORIZED:
    //   T_v[w] = sum_u a0_u * W1[u,v,w];   o_1o[w,m] += T_v[w] * b_v[m]
    // Each role handles 8 of the 16 w-channels (4 packed accumulators each).
    {
        u64 a0d[16];
#pragma unroll
        for (int u = 0; u < 16; u++) a0d[u] = dup2(xs[u * XSTR + r]);

        u64 acc1[12];
#pragma unroll
        for (int k = 0; k < 12; k++) acc1[k] = 0ULL;

        const float* w1base = ws + OFF_W1 + role * 8;

        for (int v = 0; v < 16; v++) {
            u64 T[4];
            {
                const ulonglong2* wr =
                    reinterpret_cast<const ulonglong2*>(w1base + v * 16);
                ulonglong2 w01 = wr[0], w23 = wr[1];
                T[0] = mul2(a0d[0], w01.x);
                T[1] = mul2(a0d[0], w01.y);
                T[2] = mul2(a0d[0], w23.x);
                T[3] = mul2(a0d[0], w23.y);
            }
#pragma unroll
            for (int u = 1; u < 16; u++) {
                const ulonglong2* wr =
                    reinterpret_cast<const ulonglong2*>(w1base + u * 256 + v * 16);
                ulonglong2 w01 = wr[0], w23 = wr[1];
                fma2(T[0], a0d[u], w01.x);
                fma2(T[1], a0d[u], w01.y);
                fma2(T[2], a0d[u], w23.x);
                fma2(T[3], a0d[u], w23.y);
            }
            u64 dbx = dup2(xs[(16 + 3 * v + 0) * XSTR + r]);
            u64 dby = dup2(xs[(16 + 3 * v + 1) * XSTR + r]);
            u64 dbz = dup2(xs[(16 + 3 * v + 2) * XSTR + r]);
#pragma unroll
            for (int j = 0; j < 4; j++) {
                fma2(acc1[j],     T[j], dbx);
                fma2(acc1[4 + j], T[j], dby);
                fma2(acc1[8 + j], T[j], dbz);
            }
        }
        // o_1o: this role's half -> out[16 + w*3 + m], w in [8*role, 8*role+8)
        float ob[24];
#pragma unroll
        for (int m = 0; m < 3; m++)
#pragma unroll
            for (int j = 0; j < 4; j++) {
                float lo, hi;
                unpk(acc1[m * 4 + j], lo, hi);
                ob[(2 * j) * 3 + m] = lo;
                ob[(2 * j + 1) * 3 + m] = hi;
            }
        float4* o4 = reinterpret_cast<float4*>(o + 16 + role * 24);
#pragma unroll
        for (int j = 0; j < 6; j++)
            o4[j] = make_float4(ob[4 * j], ob[4 * j + 1], ob[4 * j + 2], ob[4 * j + 3]);
    }
}

// ---------------------------------------------------------------------------
extern "C" void kernel_launch(void* const* d_in, const int* in_sizes, int n_in,
                              void* d_out, int out_size)
{
    const float* x  = (const float*)d_in[0];
    const float* w0 = (const float*)d_in[1];
    const float* w1 = (const float*)d_in[2];
    const float* w2 = (const float*)d_in[3];
    const float* w3 = (const float*)d_in[4];
    const float* w4 = (const float*)d_in[5];
    float* out = (float*)d_out;
    int n = in_sizes[0] / 64;

    cudaFuncSetAttribute(tsq_kernel, cudaFuncAttributeMaxDynamicSharedMemorySize, SMEM_BYTES);

    prep_kernel<<<16, 256>>>(w0, w1, w2, w3, w4);
    tsq_kernel<<<(n + ROWS - 1) / ROWS, BLK, SMEM_BYTES>>>(x, out, n);
}

// round 10
// speedup vs baseline: 1.1124x; 1.0756x over previous
#include <cuda_runtime.h>

typedef unsigned long long u64;

#define BLK   256
#define TROWS 256   // rows per block (2 per thread)
#define XSTR  258   // padded float stride for transposed x tile

#define OFF_S0 0        // 136*16 symmetric w0  (scaled a2)
#define OFF_S2 2176     // 136*16 symmetric w2  (scaled a2/sqrt3)
#define OFF_S4 4352     // 136*16 symmetric w4  (scaled a1; m-scales in epilogue)
#define OFF_A3 6528     // 120*16 antisym  w3   (scaled a1/sqrt2)
#define OFF_W1 8448     // 256*16 w1            (scaled a1)
#define W_TOTAL 12544
#define SMEM_FLOATS (W_TOTAL + 64 * XSTR)
#define SMEM_BYTES  (SMEM_FLOATS * 4)

#define A1F    0.0625f
#define A2F    0.04419417382415922f
#define A2_3F  0.02551551815399144f
#define A1S2F  0.04419417382415922f
#define S2F    0.7071067811865476f
#define IS6F   0.4082482904638630f

__device__ float g_ws[W_TOTAL];

__global__ void prep_kernel(const float* __restrict__ w0, const float* __restrict__ w1,
                            const float* __restrict__ w2, const float* __restrict__ w3,
                            const float* __restrict__ w4)
{
    int idx = blockIdx.x * blockDim.x + threadIdx.x;
    if (idx >= 4096) return;
    int w = idx & 15;
    int v = (idx >> 4) & 15;
    int u = idx >> 8;
    int sidx = ((v * 16 + u) << 4) + w;

    g_ws[OFF_W1 + idx] = A1F * w1[idx];

    if (u <= v) {
        int p = u * 16 - (u * (u - 1)) / 2 + (v - u);
        float f0 = (u == v) ? w0[idx] : (w0[idx] + w0[sidx]);
        float f2 = (u == v) ? w2[idx] : (w2[idx] + w2[sidx]);
        float f4 = (u == v) ? w4[idx] : (w4[idx] + w4[sidx]);
        g_ws[OFF_S0 + p * 16 + w] = A2F   * f0;
        g_ws[OFF_S2 + p * 16 + w] = A2_3F * f2;
        g_ws[OFF_S4 + p * 16 + w] = A1F   * f4;
    }
    if (u < v) {
        int pa = 15 * u - (u * (u - 1)) / 2 + (v - u - 1);
        g_ws[OFF_A3 + pa * 16 + w] = A1S2F * (w3[idx] - w3[sidx]);
    }
}

// ---- packed fp32 helpers -------------------------------------------------
__device__ __forceinline__ u64 dup2(float s)
{
    unsigned int b = __float_as_uint(s);
    u64 r;
    asm("mov.b64 %0, {%1, %1};" : "=l"(r) : "r"(b));
    return r;
}
__device__ __forceinline__ void fma2(u64& d, u64 a, u64 b)
{
    asm("fma.rn.f32x2 %0, %1, %2, %0;" : "+l"(d) : "l"(a), "l"(b));
}
__device__ __forceinline__ u64 mul2(u64 a, u64 b)
{
    u64 d;
    asm("mul.rn.f32x2 %0, %1, %2;" : "=l"(d) : "l"(a), "l"(b));
    return d;
}
__device__ __forceinline__ void unpk(u64 v, float& lo, float& hi)
{
    unsigned int l, h;
    asm("mov.b64 {%0, %1}, %2;" : "=r"(l), "=r"(h) : "l"(v));
    lo = __uint_as_float(l);
    hi = __uint_as_float(h);
}

// ---- dual-row axpy: one weight-row load feeds both rows' accumulators ----
__device__ __forceinline__ void axpy16_2(u64* aA, u64* aB, const float* wb, u64 fA, u64 fB)
{
    const ulonglong2* wr = reinterpret_cast<const ulonglong2*>(wb);
#pragma unroll
    for (int q = 0; q < 4; q++) {
        ulonglong2 wv = wr[q];
        fma2(aA[2 * q], fA, wv.x); fma2(aA[2 * q + 1], fA, wv.y);
        fma2(aB[2 * q], fB, wv.x); fma2(aB[2 * q + 1], fB, wv.y);
    }
}
__device__ __forceinline__ void axpy16x3_2(u64* aA, u64* aB, const float* wb,
                                           const u64* fA, const u64* fB)
{
    const ulonglong2* wr = reinterpret_cast<const ulonglong2*>(wb);
#pragma unroll
    for (int q = 0; q < 4; q++) {
        ulonglong2 wv = wr[q];
#pragma unroll
        for (int m = 0; m < 3; m++) {
            fma2(aA[8 * m + 2 * q], fA[m], wv.x); fma2(aA[8 * m + 2 * q + 1], fA[m], wv.y);
            fma2(aB[8 * m + 2 * q], fB[m], wv.x); fma2(aB[8 * m + 2 * q + 1], fB[m], wv.y);
        }
    }
}
__device__ __forceinline__ void axpy16x5_2(u64* aA, u64* aB, const float* wb,
                                           const u64* fA, const u64* fB)
{
    const ulonglong2* wr = reinterpret_cast<const ulonglong2*>(wb);
#pragma unroll
    for (int q = 0; q < 4; q++) {
        ulonglong2 wv = wr[q];
#pragma unroll
        for (int m = 0; m < 5; m++) {
            fma2(aA[8 * m + 2 * q], fA[m], wv.x); fma2(aA[8 * m + 2 * q + 1], fA[m], wv.y);
            fma2(aB[8 * m + 2 * q], fB[m], wv.x); fma2(aB[8 * m + 2 * q + 1], fB[m], wv.y);
        }
    }
}

// ---- output writers ------------------------------------------------------
__device__ __forceinline__ void store_0e(const u64* acc, float* o)
{
    float ob[16];
#pragma unroll
    for (int j = 0; j < 8; j++) unpk(acc[j], ob[2 * j], ob[2 * j + 1]);
    float4* o4 = reinterpret_cast<float4*>(o);
#pragma unroll
    for (int j = 0; j < 4; j++)
        o4[j] = make_float4(ob[4 * j], ob[4 * j + 1], ob[4 * j + 2], ob[4 * j + 3]);
}
__device__ __forceinline__ void store_1e(const u64* acc, float* o)
{
    float ob[48];
#pragma unroll
    for (int m = 0; m < 3; m++)
#pragma unroll
        for (int j = 0; j < 8; j++) {
            float lo, hi; unpk(acc[m * 8 + j], lo, hi);
            ob[(2 * j) * 3 + m] = lo; ob[(2 * j + 1) * 3 + m] = hi;
        }
    float4* o4 = reinterpret_cast<float4*>(o + 64);
#pragma unroll
    for (int j = 0; j < 12; j++)
        o4[j] = make_float4(ob[4 * j], ob[4 * j + 1], ob[4 * j + 2], ob[4 * j + 3]);
}
__device__ __forceinline__ void store_2e(const u64* acc, float* o)
{
    const float csc[5] = {S2F, S2F, IS6F, S2F, S2F};   // epilogue m-scales
    float ob[80];
#pragma unroll
    for (int m = 0; m < 5; m++)
#pragma unroll
        for (int j = 0; j < 8; j++) {
            float lo, hi; unpk(acc[m * 8 + j], lo, hi);
            ob[(2 * j) * 5 + m] = lo * csc[m]; ob[(2 * j + 1) * 5 + m] = hi * csc[m];
        }
    float4* o4 = reinterpret_cast<float4*>(o + 112);
#pragma unroll
    for (int j = 0; j < 20; j++)
        o4[j] = make_float4(ob[4 * j], ob[4 * j + 1], ob[4 * j + 2], ob[4 * j + 3]);
}
__device__ __forceinline__ void store_1o_half(const u64* acc, float* o, int role)
{
    float ob[24];
#pragma unroll
    for (int m = 0; m < 3; m++)
#pragma unroll
        for (int j = 0; j < 4; j++) {
            float lo, hi; unpk(acc[m * 4 + j], lo, hi);
            ob[(2 * j) * 3 + m] = lo; ob[(2 * j + 1) * 3 + m] = hi;
        }
    float4* o4 = reinterpret_cast<float4*>(o + 16 + role * 24);
#pragma unroll
    for (int j = 0; j < 6; j++)
        o4[j] = make_float4(ob[4 * j], ob[4 * j + 1], ob[4 * j + 2], ob[4 * j + 3]);
}

// ---------------------------------------------------------------------------
// 2 rows per thread (rows r and r+128 of a 256-row tile); role split by path:
//   role 0 (warps 0-3): o_2e  + o_1o[w 0..7]
//   role 1 (warps 4-7): o_0e + o_1e + o_1o[w 8..15]
// Every weight-row LDS is shared by both rows.
// ---------------------------------------------------------------------------
__global__ __launch_bounds__(BLK, 1)
void tsq_kernel(const float* __restrict__ x, float* __restrict__ out, int n)
{
    extern __shared__ float smem[];
    float* ws = smem;
    float* xs = smem + W_TOTAL;
    int tid = threadIdx.x;

    {
        const float4* gw = reinterpret_cast<const float4*>(g_ws);
        float4* sw = reinterpret_cast<float4*>(ws);
        for (int i = tid; i < W_TOTAL / 4; i += BLK) sw[i] = gw[i];
    }
    int row0 = blockIdx.x * TROWS;
    {
        const float4* x4 = reinterpret_cast<const float4*>(x);
#pragma unroll
        for (int i = 0; i < 16; i++) {
            int lin = i * BLK + tid;            // 4096 = 256 rows * 16 float4
            int rr = lin >> 4, c = lin & 15;
            float4 val = make_float4(0.f, 0.f, 0.f, 0.f);
            if (row0 + rr < n) val = x4[(size_t)(row0 + rr) * 16 + c];
            xs[(4 * c + 0) * XSTR + rr] = val.x;
            xs[(4 * c + 1) * XSTR + rr] = val.y;
            xs[(4 * c + 2) * XSTR + rr] = val.z;
            xs[(4 * c + 3) * XSTR + rr] = val.w;
        }
    }
    __syncthreads();

    int role = tid >> 7;
    int r    = tid & 127;
    int zA = row0 + r;
    if (zA >= n) return;
    int zB = zA + 128;
    bool vB = (zB < n);
    float* oA = out + (size_t)zA * 192;
    float* oB = out + (size_t)zB * 192;
    const float* xr = xs + r;

    if (role == 0) {
        // ===== o_2e, symmetric pairs, both rows share weight loads
        u64 aA[40], aB[40];
#pragma unroll
        for (int k = 0; k < 40; k++) { aA[k] = 0ULL; aB[k] = 0ULL; }
        const float* s4r = ws + OFF_S4;

        for (int u = 0; u < 16; u++) {
            const float* fu = xr + (16 + 3 * u) * XSTR;
            float axA = fu[0],   ayA = fu[XSTR],       azA = fu[2 * XSTR];
            float axB = fu[128], ayB = fu[XSTR + 128], azB = fu[2 * XSTR + 128];
            {   // diagonal (features = 2*prod; scales applied at epilogue)
                u64 dA[5], dB[5];
                {
                    float pxx = axA * axA, pyy = ayA * ayA, pzz = azA * azA;
                    float t;
                    t = axA * ayA; dA[0] = dup2(t + t);
                    t = ayA * azA; dA[1] = dup2(t + t);
                    float s = pxx + pyy; dA[2] = dup2(fmaf(2.f, pzz, -s));
                    t = axA * azA; dA[3] = dup2(t + t);
                    dA[4] = dup2(pxx - pyy);
                }
                {
                    float pxx = axB * axB, pyy = ayB * ayB, pzz = azB * azB;
                    float t;
                    t = axB * ayB; dB[0] = dup2(t + t);
                    t = ayB * azB; dB[1] = dup2(t + t);
                    float s = pxx + pyy; dB[2] = dup2(fmaf(2.f, pzz, -s));
                    t = axB * azB; dB[3] = dup2(t + t);
                    dB[4] = dup2(pxx - pyy);
                }
                axpy16x5_2(aA, aB, s4r, dA, dB); s4r += 16;
            }
            for (int v = u + 1; v < 16; v++) {
                const float* fv = xr + (16 + 3 * v) * XSTR;
                float bxA = fv[0],   byA = fv[XSTR],       bzA = fv[2 * XSTR];
                float bxB = fv[128], byB = fv[XSTR + 128], bzB = fv[2 * XSTR + 128];
                u64 dA[5], dB[5];
                {
                    float pxx = axA * bxA, pyy = ayA * byA, pzz = azA * bzA;
                    dA[0] = dup2(fmaf(axA, byA, ayA * bxA));
                    dA[1] = dup2(fmaf(ayA, bzA, azA * byA));
                    float s = pxx + pyy; dA[2] = dup2(fmaf(2.f, pzz, -s));
                    dA[3] = dup2(fmaf(axA, bzA, azA * bxA));
                    dA[4] = dup2(pxx - pyy);
                }
                {
                    float pxx = axB * bxB, pyy = ayB * byB, pzz = azB * bzB;
                    dB[0] = dup2(fmaf(axB, byB, ayB * bxB));
                    dB[1] = dup2(fmaf(ayB, bzB, azB * byB));
                    float s = pxx + pyy; dB[2] = dup2(fmaf(2.f, pzz, -s));
                    dB[3] = dup2(fmaf(axB, bzB, azB * bxB));
                    dB[4] = dup2(pxx - pyy);
                }
                axpy16x5_2(aA, aB, s4r, dA, dB); s4r += 16;
            }
        }
        store_2e(aA, oA);
        if (vB) store_2e(aB, oB);
    } else {
        // ===== o_0e (paths 0+2) and o_1e (path 3)
        u64 c0A[8], c0B[8], e1A[24], e1B[24];
#pragma unroll
        for (int k = 0; k < 8; k++)  { c0A[k] = 0ULL; c0B[k] = 0ULL; }
#pragma unroll
        for (int k = 0; k < 24; k++) { e1A[k] = 0ULL; e1B[k] = 0ULL; }
        const float* s0r = ws + OFF_S0;
        const float* s2r = ws + OFF_S2;
        const float* a3r = ws + OFF_A3;

        for (int u = 0; u < 16; u++) {
            const float* f0u = xr + u * XSTR;
            float a0A = f0u[0], a0B = f0u[128];
            const float* fu = xr + (16 + 3 * u) * XSTR;
            float axA = fu[0],   ayA = fu[XSTR],       azA = fu[2 * XSTR];
            float axB = fu[128], ayB = fu[XSTR + 128], azB = fu[2 * XSTR + 128];
            {   // diagonal
                float sA = a0A * a0A, sB = a0B * a0B;
                float dA = fmaf(axA, axA, fmaf(ayA, ayA, azA * azA));
                float dB = fmaf(axB, axB, fmaf(ayB, ayB, azB * azB));
                axpy16_2(c0A, c0B, s0r, dup2(sA), dup2(sB)); s0r += 16;
                axpy16_2(c0A, c0B, s2r, dup2(dA), dup2(dB)); s2r += 16;
            }
            for (int v = u + 1; v < 16; v++) {
                const float* f0v = xr + v * XSTR;
                float b0A = f0v[0], b0B = f0v[128];
                const float* fv = xr + (16 + 3 * v) * XSTR;
                float bxA = fv[0],   byA = fv[XSTR],       bzA = fv[2 * XSTR];
                float bxB = fv[128], byB = fv[XSTR + 128], bzB = fv[2 * XSTR + 128];

                float sA = a0A * b0A, sB = a0B * b0B;
                float dA = fmaf(axA, bxA, fmaf(ayA, byA, azA * bzA));
                float dB = fmaf(axB, bxB, fmaf(ayB, byB, azB * bzB));
                u64 cA[3], cB[3];
                cA[0] = dup2(fmaf(ayA, bzA, -(azA * byA)));
                cA[1] = dup2(fmaf(azA, bxA, -(axA * bzA)));
                cA[2] = dup2(fmaf(axA, byA, -(ayA * bxA)));
                cB[0] = dup2(fmaf(ayB, bzB, -(azB * byB)));
                cB[1] = dup2(fmaf(azB, bxB, -(axB * bzB)));
                cB[2] = dup2(fmaf(axB, byB, -(ayB * bxB)));

                axpy16_2(c0A, c0B, s0r, dup2(sA), dup2(sB)); s0r += 16;
                axpy16_2(c0A, c0B, s2r, dup2(dA), dup2(dB)); s2r += 16;
                axpy16x3_2(e1A, e1B, a3r, cA, cB);           a3r += 16;
            }
        }
        store_0e(c0A, oA);
        store_1e(e1A, oA);
        if (vB) { store_0e(c0B, oB); store_1e(e1B, oB); }
    }

    // ===== path 1 (0e x 1o -> 1o), factorized; role handles 8 of 16 w
    {
        u64 a0A[16], a0B[16];
#pragma unroll
        for (int u = 0; u < 16; u++) {
            a0A[u] = dup2(xr[u * XSTR]);
            a0B[u] = dup2(xr[u * XSTR + 128]);
        }
        u64 pA[12], pB[12];
#pragma unroll
        for (int k = 0; k < 12; k++) { pA[k] = 0ULL; pB[k] = 0ULL; }

        const float* w1b = ws + OFF_W1 + role * 8;

        for (int v = 0; v < 16; v++) {
            u64 TA[4], TB[4];
            {
                const ulonglong2* wr = reinterpret_cast<const ulonglong2*>(w1b + v * 16);
                ulonglong2 w01 = wr[0], w23 = wr[1];
                TA[0] = mul2(a0A[0], w01.x); TA[1] = mul2(a0A[0], w01.y);
                TA[2] = mul2(a0A[0], w23.x); TA[3] = mul2(a0A[0], w23.y);
                TB[0] = mul2(a0B[0], w01.x); TB[1] = mul2(a0B[0], w01.y);
                TB[2] = mul2(a0B[0], w23.x); TB[3] = mul2(a0B[0], w23.y);
            }
#pragma unroll
            for (int u = 1; u < 16; u++) {
                const ulonglong2* wr =
                    reinterpret_cast<const ulonglong2*>(w1b + u * 256 + v * 16);
                ulonglong2 w01 = wr[0], w23 = wr[1];
                fma2(TA[0], a0A[u], w01.x); fma2(TA[1], a0A[u], w01.y);
                fma2(TA[2], a0A[u], w23.x); fma2(TA[3], a0A[u], w23.y);
                fma2(TB[0], a0B[u], w01.x); fma2(TB[1], a0B[u], w01.y);
                fma2(TB[2], a0B[u], w23.x); fma2(TB[3], a0B[u], w23.y);
            }
            const float* fv = xr + (16 + 3 * v) * XSTR;
            u64 xdA = dup2(fv[0]),   ydA = dup2(fv[XSTR]),       zdA = dup2(fv[2 * XSTR]);
            u64 xdB = dup2(fv[128]), ydB = dup2(fv[XSTR + 128]), zdB = dup2(fv[2 * XSTR + 128]);
#pragma unroll
            for (int j = 0; j < 4; j++) {
                fma2(pA[j], TA[j], xdA); fma2(pA[4 + j], TA[j], ydA); fma2(pA[8 + j], TA[j], zdA);
                fma2(pB[j], TB[j], xdB); fma2(pB[4 + j], TB[j], ydB); fma2(pB[8 + j], TB[j], zdB);
            }
        }
        store_1o_half(pA, oA, role);
        if (vB) store_1o_half(pB, oB, role);
    }
}

// ---------------------------------------------------------------------------
extern "C" void kernel_launch(void* const* d_in, const int* in_sizes, int n_in,
                              void* d_out, int out_size)
{
    const float* x  = (const float*)d_in[0];
    const float* w0 = (const float*)d_in[1];
    const float* w1 = (const float*)d_in[2];
    const float* w2 = (const float*)d_in[3];
    const float* w3 = (const float*)d_in[4];
    const float* w4 = (const float*)d_in[5];
    float* out = (float*)d_out;
    int n = in_sizes[0] / 64;

    cudaFuncSetAttribute(tsq_kernel, cudaFuncAttributeMaxDynamicSharedMemorySize, SMEM_BYTES);

    prep_kernel<<<16, 256>>>(w0, w1, w2, w3, w4);
    tsq_kernel<<<(n + TROWS - 1) / TROWS, BLK, SMEM_BYTES>>>(x, out, n);
}